// round 7
// baseline (speedup 1.0000x reference)
#include <cuda_runtime.h>
#include <cuda_fp16.h>
#include <cstdint>
#include <cstddef>

#define TT 16
#define HEADS 8
#define DH 40
#define CC 320
#define SPATIAL 1024
#define NSLAB 64
#define SLAB (CC * SPATIAL)
#define NELEM (1ull * NSLAB * SLAB)   // 20,971,520

// fp16 scratch: Q,K,V,O, Xh (5 x NELEM) + 4 converted W matrices
__device__ __half g_hbuf[5ull * NELEM + 4ull * CC * CC];

// ================= helpers =================
__device__ __forceinline__ uint32_t smem_u32(const void* p) {
    uint32_t a;
    asm("{ .reg .u64 t; cvta.to.shared.u64 t, %1; cvt.u32.u64 %0, t; }"
        : "=r"(a) : "l"(p));
    return a;
}
__device__ __forceinline__ void ldsm4(uint32_t* r, uint32_t a) {
    asm volatile("ldmatrix.sync.aligned.m8n8.x4.shared.b16 {%0,%1,%2,%3}, [%4];"
                 : "=r"(r[0]), "=r"(r[1]), "=r"(r[2]), "=r"(r[3]) : "r"(a));
}
__device__ __forceinline__ void ldsm4t(uint32_t* r, uint32_t a) {
    asm volatile("ldmatrix.sync.aligned.m8n8.x4.trans.shared.b16 {%0,%1,%2,%3}, [%4];"
                 : "=r"(r[0]), "=r"(r[1]), "=r"(r[2]), "=r"(r[3]) : "r"(a));
}
__device__ __forceinline__ void mma16(float* c, const uint32_t* a,
                                      uint32_t b0, uint32_t b1) {
    asm volatile(
        "mma.sync.aligned.m16n8k16.row.col.f32.f16.f16.f32 "
        "{%0,%1,%2,%3},{%4,%5,%6,%7},{%8,%9},{%0,%1,%2,%3};"
        : "+f"(c[0]), "+f"(c[1]), "+f"(c[2]), "+f"(c[3])
        : "r"(a[0]), "r"(a[1]), "r"(a[2]), "r"(a[3]), "r"(b0), "r"(b1));
}
#define CP_ASYNC(dst, src, sz) \
    asm volatile("cp.async.cg.shared.global [%0], [%1], 16, %2;" \
                 :: "r"(dst), "l"(src), "r"(sz))
#define CP_COMMIT() asm volatile("cp.async.commit_group;" ::: "memory")

// ================= conversion kernels =================
__global__ __launch_bounds__(256) void cvt_x(const float* __restrict__ x,
                                             __half* __restrict__ xh) {
    const size_t i = ((size_t)blockIdx.x * 256 + threadIdx.x) * 8;
    float4 a = *(const float4*)(x + i);
    float4 b = *(const float4*)(x + i + 4);
    __half2 h[4] = { __floats2half2_rn(a.x, a.y), __floats2half2_rn(a.z, a.w),
                     __floats2half2_rn(b.x, b.y), __floats2half2_rn(b.z, b.w) };
    *(uint4*)(xh + i) = *(uint4*)h;
}
__global__ void cvt_w(const float* __restrict__ Wq, const float* __restrict__ Wk,
                      const float* __restrict__ Wv, const float* __restrict__ Wo,
                      __half* __restrict__ dst) {
    const int z = blockIdx.y;
    const int i = blockIdx.x * 1024 + threadIdx.x;   // < 102400
    const float* s = (z == 0) ? Wq : (z == 1) ? Wk : (z == 2) ? Wv : Wo;
    dst[(size_t)z * CC * CC + i] = __float2half_rn(s[i]);
}

// ================= fp16 tensor-core GEMM =================
// C[m0:+128, n0:+128] = W[320,320] @ X[320,1024] (K=320, 10 tiles of BK=32)
// 8 warps (2m x 4n), warp tile 64x32, mma.m16n8k16, fp32 accum.
// 4-stage cp.async ring, single __syncthreads per k-iter.
#define APITCH 40
#define BPITCH 136
#define STAGEB 18944

template <bool EPI>
__device__ __forceinline__ void tc_gemm(
    const __half* __restrict__ W, const __half* __restrict__ X,
    void* __restrict__ Cout, const float* __restrict__ bias,
    const float* __restrict__ R, int m0, int n0)
{
    extern __shared__ char smem[];
    const int tid = threadIdx.x;
    const int lane = tid & 31, wid = tid >> 5;
    const int wm = (wid & 1) * 64, wn = (wid >> 1) * 32;
    const uint32_t sb = smem_u32(smem);

    float c[4][4][4];
#pragma unroll
    for (int a = 0; a < 4; a++)
#pragma unroll
        for (int b = 0; b < 4; b++)
#pragma unroll
            for (int d = 0; d < 4; d++) c[a][b][d] = 0.f;

    auto stage = [&](int i) {
        const int kt = i * 32;
        const uint32_t as = sb + (uint32_t)(i & 3) * STAGEB;
        const uint32_t bs = as + 10240u;
#pragma unroll
        for (int t = 0; t < 2; t++) {
            const int idx = t * 256 + tid;
            const int row = idx >> 2, ch = idx & 3;
            const __half* src = W + (size_t)(m0 + row) * CC + kt + ch * 8;
            const int sz = (m0 + row < CC) ? 16 : 0;
            CP_ASYNC(as + (uint32_t)(row * (APITCH * 2) + ch * 16), src, sz);
        }
#pragma unroll
        for (int t = 0; t < 2; t++) {
            const int idx = t * 256 + tid;
            const int k = idx >> 4, nc = idx & 15;
            const __half* src = X + (size_t)(kt + k) * SPATIAL + n0 + nc * 8;
            CP_ASYNC(bs + (uint32_t)(k * (BPITCH * 2) + nc * 16), src, 16);
        }
        CP_COMMIT();
    };

    stage(0);
    stage(1);
    stage(2);

    for (int i = 0; i < 10; i++) {
        if (i < 8)       asm volatile("cp.async.wait_group 2;" ::: "memory");
        else if (i == 8) asm volatile("cp.async.wait_group 1;" ::: "memory");
        else             asm volatile("cp.async.wait_group 0;" ::: "memory");
        __syncthreads();
        if (i + 3 < 10) stage(i + 3);

        const uint32_t as = sb + (uint32_t)(i & 3) * STAGEB;
        const uint32_t bs = as + 10240u;

#pragma unroll
        for (int ks = 0; ks < 2; ks++) {
            uint32_t af[4][4], bf[2][4];
#pragma unroll
            for (int mt = 0; mt < 4; mt++) {
                const uint32_t addr = as +
                    (uint32_t)((wm + mt * 16 + (lane & 15)) * (APITCH * 2) +
                               (lane >> 4) * 16 + ks * 32);
                ldsm4(af[mt], addr);
            }
#pragma unroll
            for (int nb = 0; nb < 2; nb++) {
                const uint32_t addr = bs +
                    (uint32_t)((ks * 16 + (lane & 15)) * (BPITCH * 2) +
                               (wn + nb * 16 + (lane >> 4) * 8) * 2);
                ldsm4t(bf[nb], addr);
            }
#pragma unroll
            for (int nt = 0; nt < 4; nt++) {
                const uint32_t b0 = bf[nt >> 1][(nt & 1) * 2];
                const uint32_t b1 = bf[nt >> 1][(nt & 1) * 2 + 1];
#pragma unroll
                for (int mt = 0; mt < 4; mt++)
                    mma16(c[mt][nt], af[mt], b0, b1);
            }
        }
    }

    // ---- epilogue ----
#pragma unroll
    for (int mt = 0; mt < 4; mt++) {
#pragma unroll
        for (int nt = 0; nt < 4; nt++) {
            const int r0 = m0 + wm + mt * 16 + (lane >> 2);
            const int col = n0 + wn + nt * 8 + (lane & 3) * 2;
            if (EPI) {
                float* C = (float*)Cout;
                if (r0 < CC) {
                    const size_t o0 = (size_t)r0 * SPATIAL + col;
                    const float bb = bias[r0];
                    const float2 x0 = *(const float2*)(R + o0);
                    *(float2*)(C + o0) = make_float2(c[mt][nt][0] + bb + x0.x,
                                                     c[mt][nt][1] + bb + x0.y);
                }
                if (r0 + 8 < CC) {
                    const size_t o1 = (size_t)(r0 + 8) * SPATIAL + col;
                    const float bb = bias[r0 + 8];
                    const float2 x1 = *(const float2*)(R + o1);
                    *(float2*)(C + o1) = make_float2(c[mt][nt][2] + bb + x1.x,
                                                     c[mt][nt][3] + bb + x1.y);
                }
            } else {
                __half* C = (__half*)Cout;
                if (r0 < CC) {
                    *(__half2*)(C + (size_t)r0 * SPATIAL + col) =
                        __floats2half2_rn(c[mt][nt][0], c[mt][nt][1]);
                }
                if (r0 + 8 < CC) {
                    *(__half2*)(C + (size_t)(r0 + 8) * SPATIAL + col) =
                        __floats2half2_rn(c[mt][nt][2], c[mt][nt][3]);
                }
            }
        }
    }
}

__global__ __launch_bounds__(256, 2) void qkv_tc(
    const __half* __restrict__ Wh, const __half* __restrict__ Xh,
    __half* __restrict__ out)
{
    const int slab = blockIdx.z;
    const int wsel = blockIdx.y / 3, mt = blockIdx.y % 3;
    tc_gemm<false>(Wh + (size_t)wsel * CC * CC, Xh + (size_t)slab * SLAB,
                   out + (size_t)wsel * NELEM + (size_t)slab * SLAB,
                   nullptr, nullptr, mt * 128, blockIdx.x * 128);
}

__global__ __launch_bounds__(256, 2) void o_tc(
    const __half* __restrict__ Wh, const __half* __restrict__ O,
    const float* __restrict__ bo, const float* __restrict__ X,
    float* __restrict__ out)
{
    const int slab = blockIdx.z;
    tc_gemm<true>(Wh + 3ull * CC * CC, O + (size_t)slab * SLAB,
                  out + (size_t)slab * SLAB, bo, X + (size_t)slab * SLAB,
                  blockIdx.y * 128, blockIdx.x * 128);
}

// ================= Attention (fp16 I/O, fp32 accum, half2 SIMD loads) =========
// Block = (b, h, 32 spatial). 256 thr = 8 warps; warp tg does t=tg, t=15-tg.
// K,V packed in smem as half2 [frame][dpair j][32 lanes] (conflict-free 4B LDS);
// rel tables packed half2 [diff][dpair] (broadcast LDS). 87.2KB -> 2 CTA/SM.
#define DP (DH / 2)   // 20 d-pairs

__global__ __launch_bounds__(256, 2) void attn_kernel(
    const __half* __restrict__ Qg, const __half* __restrict__ Kg,
    const __half* __restrict__ Vg, __half* __restrict__ Og,
    const float* __restrict__ relk, const float* __restrict__ relv)
{
    extern __shared__ char smc[];
    __half2* Ks2 = (__half2*)smc;                 // 16*20*32 = 10240 words
    __half2* Vs2 = Ks2 + TT * DP * 32;            // 10240 words
    __half2* Rk2 = Vs2 + TT * DP * 32;            // 33*20 = 660
    __half2* Rv2 = Rk2 + 33 * DP;                 // 660   (total 87200 B)

    const int b = blockIdx.z;
    const int h = blockIdx.y;
    const int s0 = blockIdx.x * 32;
    const int tid = threadIdx.x;

    // stage K,V: coalesced gmem half reads, u16 scatter into pair layout
    __half* Ksh = (__half*)Ks2;
    __half* Vsh = (__half*)Vs2;
    for (int i = tid; i < TT * DH * 32; i += 256) {
        const int row = i >> 5, sl2 = i & 31;
        const int f = row / DH, dd = row - f * DH;
        const size_t g =
            ((size_t)((b * TT + f) * CC + h * DH + dd)) * SPATIAL + s0 + sl2;
        const int w = ((f * DP + (dd >> 1)) * 32 + sl2) * 2 + (dd & 1);
        Ksh[w] = Kg[g];
        Vsh[w] = Vg[g];
    }
    for (int i = tid; i < 33 * DP; i += 256) {
        const int diff = i / DP, j = i - diff * DP;
        Rk2[i] = __floats2half2_rn(relk[diff * DH + 2 * j],
                                   relk[diff * DH + 2 * j + 1]);
        Rv2[i] = __floats2half2_rn(relv[diff * DH + 2 * j],
                                   relv[diff * DH + 2 * j + 1]);
    }
    __syncthreads();

    const int sl = tid & 31;
    const int tg = tid >> 5;
    const float scale = 0.15811388300841898f;  // 40^-0.5

    for (int rep = 0; rep < 2; rep++) {
        const int t = rep ? (15 - tg) : tg;    // warp-uniform
        const size_t base =
            ((size_t)((b * TT + t) * CC + h * DH)) * SPATIAL + s0 + sl;

        float q[DH];
#pragma unroll
        for (int dd = 0; dd < DH; dd++)
            q[dd] = __half2float(Qg[base + (size_t)dd * SPATIAL]);

        float sim[TT];
        float mx = -1e30f;
#pragma unroll
        for (int sp = 0; sp < TT; sp++) {
            if (sp > t) break;                 // warp-uniform
            const __half2* kp = Ks2 + (sp * DP) * 32 + sl;
            const __half2* rp = Rk2 + (sp - t + TT) * DP;
            float p0 = 0.f, p1 = 0.f, p2 = 0.f, p3 = 0.f;
#pragma unroll
            for (int j = 0; j < DP; j++) {
                const float2 f2 = __half22float2(__hadd2(kp[j * 32], rp[j]));
                if (j & 1) {
                    p2 = fmaf(q[2 * j], f2.x, p2);
                    p3 = fmaf(q[2 * j + 1], f2.y, p3);
                } else {
                    p0 = fmaf(q[2 * j], f2.x, p0);
                    p1 = fmaf(q[2 * j + 1], f2.y, p1);
                }
            }
            const float acc = ((p0 + p1) + (p2 + p3)) * scale;
            sim[sp] = acc;
            mx = fmaxf(mx, acc);
        }
        float den = 0.f;
#pragma unroll
        for (int sp = 0; sp < TT; sp++) {
            if (sp > t) break;
            const float e = __expf(sim[sp] - mx);
            sim[sp] = e;
            den += e;
        }
        const float inv = 1.f / den;

        float o[DH];
#pragma unroll
        for (int dd = 0; dd < DH; dd++) o[dd] = 0.f;
#pragma unroll
        for (int sp = 0; sp < TT; sp++) {
            if (sp > t) break;
            const float a = sim[sp];
            const __half2* vp = Vs2 + (sp * DP) * 32 + sl;
            const __half2* rp = Rv2 + (sp - t + TT) * DP;
#pragma unroll
            for (int j = 0; j < DP; j++) {
                const float2 f2 = __half22float2(__hadd2(vp[j * 32], rp[j]));
                o[2 * j]     = fmaf(a, f2.x, o[2 * j]);
                o[2 * j + 1] = fmaf(a, f2.y, o[2 * j + 1]);
            }
        }
#pragma unroll
        for (int dd = 0; dd < DH; dd++)
            Og[base + (size_t)dd * SPATIAL] = __float2half_rn(o[dd] * inv);
    }
}

// ================= launch =================
extern "C" void kernel_launch(void* const* d_in, const int* in_sizes, int n_in,
                              void* d_out, int out_size) {
    const float* x  = (const float*)d_in[0];
    const float* Wq = (const float*)d_in[1];
    const float* Wk = (const float*)d_in[2];
    const float* Wv = (const float*)d_in[3];
    const float* Wo = (const float*)d_in[4];
    const float* bo = (const float*)d_in[5];
    const float* rk = (const float*)d_in[6];
    const float* rv = (const float*)d_in[7];
    float* out = (float*)d_out;

    __half* hb = nullptr;
    cudaGetSymbolAddress((void**)&hb, g_hbuf);
    __half* Q  = hb;
    __half* K  = hb + 1ull * NELEM;
    __half* V  = hb + 2ull * NELEM;
    __half* O  = hb + 3ull * NELEM;
    __half* Xh = hb + 4ull * NELEM;
    __half* Wh = hb + 5ull * NELEM;

    cvt_w<<<dim3(100, 4), 1024>>>(Wq, Wk, Wv, Wo, Wh);
    cvt_x<<<(unsigned)(NELEM / (256 * 8)), 256>>>(x, Xh);

    const int gsm = 4 * STAGEB;  // 75776
    cudaFuncSetAttribute((const void*)qkv_tc,
                         cudaFuncAttributeMaxDynamicSharedMemorySize, gsm);
    cudaFuncSetAttribute((const void*)o_tc,
                         cudaFuncAttributeMaxDynamicSharedMemorySize, gsm);

    qkv_tc<<<dim3(SPATIAL / 128, 9, NSLAB), 256, gsm>>>(Wh, Xh, hb);

    const int asmb = (2 * TT * DP * 32 + 2 * 33 * DP) * 4;  // 87200
    cudaFuncSetAttribute((const void*)attn_kernel,
                         cudaFuncAttributeMaxDynamicSharedMemorySize, asmb);
    attn_kernel<<<dim3(SPATIAL / 32, HEADS, 4), 256, asmb>>>(Q, K, V, O, rk, rv);

    o_tc<<<dim3(SPATIAL / 128, 3, NSLAB), 256, gsm>>>(Wh, O, bo, x, out);
}

// round 8
// speedup vs baseline: 1.0264x; 1.0264x over previous
#include <cuda_runtime.h>
#include <cuda_fp16.h>
#include <cstdint>
#include <cstddef>

#define TT 16
#define HEADS 8
#define DH 40
#define CC 320
#define SPATIAL 1024
#define NSLAB 64
#define SLAB (CC * SPATIAL)
#define NELEM (1ull * NSLAB * SLAB)   // 20,971,520

// fp16 scratch: Q,K,V,O, Xh (5 x NELEM) + 4 converted W matrices
__device__ __half g_hbuf[5ull * NELEM + 4ull * CC * CC];

// ================= helpers =================
__device__ __forceinline__ uint32_t smem_u32(const void* p) {
    uint32_t a;
    asm("{ .reg .u64 t; cvta.to.shared.u64 t, %1; cvt.u32.u64 %0, t; }"
        : "=r"(a) : "l"(p));
    return a;
}
__device__ __forceinline__ void ldsm4(uint32_t* r, uint32_t a) {
    asm volatile("ldmatrix.sync.aligned.m8n8.x4.shared.b16 {%0,%1,%2,%3}, [%4];"
                 : "=r"(r[0]), "=r"(r[1]), "=r"(r[2]), "=r"(r[3]) : "r"(a));
}
__device__ __forceinline__ void ldsm4t(uint32_t* r, uint32_t a) {
    asm volatile("ldmatrix.sync.aligned.m8n8.x4.trans.shared.b16 {%0,%1,%2,%3}, [%4];"
                 : "=r"(r[0]), "=r"(r[1]), "=r"(r[2]), "=r"(r[3]) : "r"(a));
}
__device__ __forceinline__ void mma16(float* c, const uint32_t* a,
                                      uint32_t b0, uint32_t b1) {
    asm volatile(
        "mma.sync.aligned.m16n8k16.row.col.f32.f16.f16.f32 "
        "{%0,%1,%2,%3},{%4,%5,%6,%7},{%8,%9},{%0,%1,%2,%3};"
        : "+f"(c[0]), "+f"(c[1]), "+f"(c[2]), "+f"(c[3])
        : "r"(a[0]), "r"(a[1]), "r"(a[2]), "r"(a[3]), "r"(b0), "r"(b1));
}
#define CP_ASYNC(dst, src, sz) \
    asm volatile("cp.async.cg.shared.global [%0], [%1], 16, %2;" \
                 :: "r"(dst), "l"(src), "r"(sz))
#define CP_COMMIT() asm volatile("cp.async.commit_group;" ::: "memory")

// ================= conversion kernels =================
__global__ __launch_bounds__(256) void cvt_x(const float* __restrict__ x,
                                             __half* __restrict__ xh) {
    const size_t i = ((size_t)blockIdx.x * 256 + threadIdx.x) * 8;
    float4 a = *(const float4*)(x + i);
    float4 b = *(const float4*)(x + i + 4);
    __half2 h[4] = { __floats2half2_rn(a.x, a.y), __floats2half2_rn(a.z, a.w),
                     __floats2half2_rn(b.x, b.y), __floats2half2_rn(b.z, b.w) };
    *(uint4*)(xh + i) = *(uint4*)h;
}
__global__ void cvt_w(const float* __restrict__ Wq, const float* __restrict__ Wk,
                      const float* __restrict__ Wv, const float* __restrict__ Wo,
                      __half* __restrict__ dst) {
    const int z = blockIdx.y;
    const int i = blockIdx.x * 1024 + threadIdx.x;   // < 102400
    const float* s = (z == 0) ? Wq : (z == 1) ? Wk : (z == 2) ? Wv : Wo;
    dst[(size_t)z * CC * CC + i] = __float2half_rn(s[i]);
}

// ================= fp16 tensor-core GEMM (round-6 3-stage, known good) ========
#define APITCH 40
#define BPITCH 136
#define STAGEB 18944

template <bool EPI>
__device__ __forceinline__ void tc_gemm(
    const __half* __restrict__ W, const __half* __restrict__ X,
    void* __restrict__ Cout, const float* __restrict__ bias,
    const float* __restrict__ R, int m0, int n0)
{
    extern __shared__ char smem[];
    const int tid = threadIdx.x;
    const int lane = tid & 31, wid = tid >> 5;
    const int wm = (wid & 1) * 64, wn = (wid >> 1) * 32;
    const uint32_t sb = smem_u32(smem);

    float c[4][4][4];
#pragma unroll
    for (int a = 0; a < 4; a++)
#pragma unroll
        for (int b = 0; b < 4; b++)
#pragma unroll
            for (int d = 0; d < 4; d++) c[a][b][d] = 0.f;

    auto stage = [&](int i) {
        const int kt = i * 32;
        const uint32_t as = sb + (uint32_t)(i % 3) * STAGEB;
        const uint32_t bs = as + 10240u;
#pragma unroll
        for (int t = 0; t < 2; t++) {
            const int idx = t * 256 + tid;
            const int row = idx >> 2, ch = idx & 3;
            const __half* src = W + (size_t)(m0 + row) * CC + kt + ch * 8;
            const int sz = (m0 + row < CC) ? 16 : 0;
            CP_ASYNC(as + (uint32_t)(row * (APITCH * 2) + ch * 16), src, sz);
        }
#pragma unroll
        for (int t = 0; t < 2; t++) {
            const int idx = t * 256 + tid;
            const int k = idx >> 4, nc = idx & 15;
            const __half* src = X + (size_t)(kt + k) * SPATIAL + n0 + nc * 8;
            CP_ASYNC(bs + (uint32_t)(k * (BPITCH * 2) + nc * 16), src, 16);
        }
        CP_COMMIT();
    };

    stage(0);
    stage(1);

    for (int i = 0; i < 10; i++) {
        if (i < 8) asm volatile("cp.async.wait_group 1;" ::: "memory");
        else       asm volatile("cp.async.wait_group 0;" ::: "memory");
        __syncthreads();
        if (i + 2 < 10) stage(i + 2);

        const uint32_t as = sb + (uint32_t)(i % 3) * STAGEB;
        const uint32_t bs = as + 10240u;

#pragma unroll
        for (int ks = 0; ks < 2; ks++) {
            uint32_t af[4][4], bf[2][4];
#pragma unroll
            for (int mt = 0; mt < 4; mt++) {
                const uint32_t addr = as +
                    (uint32_t)((wm + mt * 16 + (lane & 15)) * (APITCH * 2) +
                               (lane >> 4) * 16 + ks * 32);
                ldsm4(af[mt], addr);
            }
#pragma unroll
            for (int nb = 0; nb < 2; nb++) {
                const uint32_t addr = bs +
                    (uint32_t)((ks * 16 + (lane & 15)) * (BPITCH * 2) +
                               (wn + nb * 16 + (lane >> 4) * 8) * 2);
                ldsm4t(bf[nb], addr);
            }
#pragma unroll
            for (int nt = 0; nt < 4; nt++) {
                const uint32_t b0 = bf[nt >> 1][(nt & 1) * 2];
                const uint32_t b1 = bf[nt >> 1][(nt & 1) * 2 + 1];
#pragma unroll
                for (int mt = 0; mt < 4; mt++)
                    mma16(c[mt][nt], af[mt], b0, b1);
            }
        }
        __syncthreads();
    }

    // ---- epilogue ----
#pragma unroll
    for (int mt = 0; mt < 4; mt++) {
#pragma unroll
        for (int nt = 0; nt < 4; nt++) {
            const int r0 = m0 + wm + mt * 16 + (lane >> 2);
            const int col = n0 + wn + nt * 8 + (lane & 3) * 2;
            if (EPI) {
                float* C = (float*)Cout;
                if (r0 < CC) {
                    const size_t o0 = (size_t)r0 * SPATIAL + col;
                    const float bb = bias[r0];
                    const float2 x0 = *(const float2*)(R + o0);
                    *(float2*)(C + o0) = make_float2(c[mt][nt][0] + bb + x0.x,
                                                     c[mt][nt][1] + bb + x0.y);
                }
                if (r0 + 8 < CC) {
                    const size_t o1 = (size_t)(r0 + 8) * SPATIAL + col;
                    const float bb = bias[r0 + 8];
                    const float2 x1 = *(const float2*)(R + o1);
                    *(float2*)(C + o1) = make_float2(c[mt][nt][2] + bb + x1.x,
                                                     c[mt][nt][3] + bb + x1.y);
                }
            } else {
                __half* C = (__half*)Cout;
                if (r0 < CC) {
                    *(__half2*)(C + (size_t)r0 * SPATIAL + col) =
                        __floats2half2_rn(c[mt][nt][0], c[mt][nt][1]);
                }
                if (r0 + 8 < CC) {
                    *(__half2*)(C + (size_t)(r0 + 8) * SPATIAL + col) =
                        __floats2half2_rn(c[mt][nt][2], c[mt][nt][3]);
                }
            }
        }
    }
}

__global__ __launch_bounds__(256, 2) void qkv_tc(
    const __half* __restrict__ Wh, const __half* __restrict__ Xh,
    __half* __restrict__ out)
{
    const int slab = blockIdx.z;
    const int wsel = blockIdx.y / 3, mt = blockIdx.y % 3;
    tc_gemm<false>(Wh + (size_t)wsel * CC * CC, Xh + (size_t)slab * SLAB,
                   out + (size_t)wsel * NELEM + (size_t)slab * SLAB,
                   nullptr, nullptr, mt * 128, blockIdx.x * 128);
}

__global__ __launch_bounds__(256, 2) void o_tc(
    const __half* __restrict__ Wh, const __half* __restrict__ O,
    const float* __restrict__ bo, const float* __restrict__ X,
    float* __restrict__ out)
{
    const int slab = blockIdx.z;
    tc_gemm<true>(Wh + 3ull * CC * CC, O + (size_t)slab * SLAB,
                  out + (size_t)slab * SLAB, bo, X + (size_t)slab * SLAB,
                  blockIdx.y * 128, blockIdx.x * 128);
}

// ================= Attention =================
// Block = (b, h, 16 spatial lanes). 256 thr = 16 groups x 16 lanes;
// group tg == query frame t (one-shot, no rep loop). K,V half2 smem
// [frame][dpair][16 lanes]; rel tables half2. 46.2KB smem, <=84 regs
// (qo[] reused for q then o) -> 3 CTAs/SM.
#define DP (DH / 2)   // 20 d-pairs
#define AL 16         // lanes per block

__global__ __launch_bounds__(256, 3) void attn_kernel(
    const __half* __restrict__ Qg, const __half* __restrict__ Kg,
    const __half* __restrict__ Vg, __half* __restrict__ Og,
    const float* __restrict__ relk, const float* __restrict__ relv)
{
    extern __shared__ char smc[];
    __half2* Ks2 = (__half2*)smc;                 // 16*20*16 = 5120 words
    __half2* Vs2 = Ks2 + TT * DP * AL;            // 5120 words
    __half2* Rk2 = Vs2 + TT * DP * AL;            // 660
    __half2* Rv2 = Rk2 + 33 * DP;                 // 660   (total 46240 B)

    const int b = blockIdx.z;
    const int h = blockIdx.y;
    const int s0 = blockIdx.x * AL;
    const int tid = threadIdx.x;

    // stage K,V: coalesced 32B gmem rows, u16 scatter into pair layout
    __half* Ksh = (__half*)Ks2;
    __half* Vsh = (__half*)Vs2;
    for (int i = tid; i < TT * DH * AL; i += 256) {
        const int row = i >> 4, sl2 = i & (AL - 1);
        const int f = row / DH, dd = row - f * DH;
        const size_t g =
            ((size_t)((b * TT + f) * CC + h * DH + dd)) * SPATIAL + s0 + sl2;
        const int w = ((f * DP + (dd >> 1)) * AL + sl2) * 2 + (dd & 1);
        Ksh[w] = Kg[g];
        Vsh[w] = Vg[g];
    }
    for (int i = tid; i < 33 * DP; i += 256) {
        const int diff = i / DP, j = i - diff * DP;
        Rk2[i] = __floats2half2_rn(relk[diff * DH + 2 * j],
                                   relk[diff * DH + 2 * j + 1]);
        Rv2[i] = __floats2half2_rn(relv[diff * DH + 2 * j],
                                   relv[diff * DH + 2 * j + 1]);
    }
    __syncthreads();

    const int sl = tid & (AL - 1);
    const int t = tid >> 4;                     // query frame, 0..15
    const float scale = 0.15811388300841898f;  // 40^-0.5

    const size_t base =
        ((size_t)((b * TT + t) * CC + h * DH)) * SPATIAL + s0 + sl;

    float qo[DH];   // q during sim phase, o during AV phase (reg reuse)
#pragma unroll
    for (int dd = 0; dd < DH; dd++)
        qo[dd] = __half2float(Qg[base + (size_t)dd * SPATIAL]);

    float sim[TT];
    float mx = -1e30f;
#pragma unroll
    for (int sp = 0; sp < TT; sp++) {
        if (sp <= t) {
            const __half2* kp = Ks2 + (sp * DP) * AL + sl;
            const __half2* rp = Rk2 + (sp - t + TT) * DP;
            float p0 = 0.f, p1 = 0.f, p2 = 0.f, p3 = 0.f;
#pragma unroll
            for (int j = 0; j < DP; j++) {
                const float2 f2 = __half22float2(__hadd2(kp[j * AL], rp[j]));
                if (j & 1) {
                    p2 = fmaf(qo[2 * j], f2.x, p2);
                    p3 = fmaf(qo[2 * j + 1], f2.y, p3);
                } else {
                    p0 = fmaf(qo[2 * j], f2.x, p0);
                    p1 = fmaf(qo[2 * j + 1], f2.y, p1);
                }
            }
            const float acc = ((p0 + p1) + (p2 + p3)) * scale;
            sim[sp] = acc;
            mx = fmaxf(mx, acc);
        }
    }
    float den = 0.f;
#pragma unroll
    for (int sp = 0; sp < TT; sp++) {
        if (sp <= t) {
            const float e = __expf(sim[sp] - mx);
            sim[sp] = e;
            den += e;
        }
    }
    const float inv = 1.f / den;

#pragma unroll
    for (int dd = 0; dd < DH; dd++) qo[dd] = 0.f;   // q dead; reuse as o
#pragma unroll
    for (int sp = 0; sp < TT; sp++) {
        if (sp <= t) {
            const float a = sim[sp];
            const __half2* vp = Vs2 + (sp * DP) * AL + sl;
            const __half2* rp = Rv2 + (sp - t + TT) * DP;
#pragma unroll
            for (int j = 0; j < DP; j++) {
                const float2 f2 = __half22float2(__hadd2(vp[j * AL], rp[j]));
                qo[2 * j]     = fmaf(a, f2.x, qo[2 * j]);
                qo[2 * j + 1] = fmaf(a, f2.y, qo[2 * j + 1]);
            }
        }
    }
#pragma unroll
    for (int dd = 0; dd < DH; dd++)
        Og[base + (size_t)dd * SPATIAL] = __float2half_rn(qo[dd] * inv);
}

// ================= launch =================
extern "C" void kernel_launch(void* const* d_in, const int* in_sizes, int n_in,
                              void* d_out, int out_size) {
    const float* x  = (const float*)d_in[0];
    const float* Wq = (const float*)d_in[1];
    const float* Wk = (const float*)d_in[2];
    const float* Wv = (const float*)d_in[3];
    const float* Wo = (const float*)d_in[4];
    const float* bo = (const float*)d_in[5];
    const float* rk = (const float*)d_in[6];
    const float* rv = (const float*)d_in[7];
    float* out = (float*)d_out;

    __half* hb = nullptr;
    cudaGetSymbolAddress((void**)&hb, g_hbuf);
    __half* Q  = hb;
    __half* K  = hb + 1ull * NELEM;
    __half* V  = hb + 2ull * NELEM;
    __half* O  = hb + 3ull * NELEM;
    __half* Xh = hb + 4ull * NELEM;
    __half* Wh = hb + 5ull * NELEM;

    cvt_w<<<dim3(100, 4), 1024>>>(Wq, Wk, Wv, Wo, Wh);
    cvt_x<<<(unsigned)(NELEM / (256 * 8)), 256>>>(x, Xh);

    const int gsm = 3 * STAGEB;  // 56832
    cudaFuncSetAttribute((const void*)qkv_tc,
                         cudaFuncAttributeMaxDynamicSharedMemorySize, gsm);
    cudaFuncSetAttribute((const void*)o_tc,
                         cudaFuncAttributeMaxDynamicSharedMemorySize, gsm);

    qkv_tc<<<dim3(SPATIAL / 128, 9, NSLAB), 256, gsm>>>(Wh, Xh, hb);

    const int asmb = (2 * TT * DP * AL + 2 * 33 * DP) * 4;  // 46240
    cudaFuncSetAttribute((const void*)attn_kernel,
                         cudaFuncAttributeMaxDynamicSharedMemorySize, asmb);
    attn_kernel<<<dim3(SPATIAL / AL, HEADS, 4), 256, asmb>>>(Q, K, V, O, rk, rv);

    o_tc<<<dim3(SPATIAL / 128, 3, NSLAB), 256, gsm>>>(Wh, O, bo, x, out);
}